// round 1
// baseline (speedup 1.0000x reference)
#include <cuda_runtime.h>
#include <cuda_bf16.h>

#define HH   1024
#define NN   32
#define LL   4096
#define MM   2048          // LL/2, size of the complex IFFT
#define LF   2049          // LL/2 + 1
#define NTHR 256

__device__ __forceinline__ float frcp(float x) {
    float r;
    asm("rcp.approx.ftz.f32 %0, %1;" : "=f"(r) : "f"(x));
    return r;
}

__global__ __launch_bounds__(NTHR)
void dplr_kernel(const float* __restrict__ log_dt,
                 const float* __restrict__ A_re, const float* __restrict__ A_im,
                 const float* __restrict__ B_re, const float* __restrict__ B_im,
                 const float* __restrict__ C_re, const float* __restrict__ C_im,
                 const float* __restrict__ P_re, const float* __restrict__ P_im,
                 float* __restrict__ out)
{
    // ping-pong FFT buffers: fbuf[0..MM) = A half, fbuf[MM..2MM) = B half
    __shared__ float2 fbuf[2 * MM];          // 32 KB
    __shared__ float2 wpack[NN];             // (wr, |w|^2) per conj pair
    __shared__ float4 upack[NN];             // dt * Re(v_ab * conj(w)) for ab=00,01,10,11
    __shared__ float4 vpack[NN];             // dt * Re(v_ab)
    __shared__ float2 kf_last;               // k_f[L/2]

    const int h   = blockIdx.x;
    const int tid = threadIdx.x;

    // ---------------- Phase 1: per-head pole / numerator tables ----------------
    if (tid < NN) {
        const int n   = tid;
        const int idx = h * NN + n;
        const float dt = expf(log_dt[h]);
        const float wr = dt * A_re[idx];
        const float wi = dt * A_im[idx];
        const float Br = B_re[idx], Bi = B_im[idx];
        const float Cr = C_re[idx], Ci = C_im[idx];
        const float Pr = P_re[idx], Pi = P_im[idx];

        // v00 = B*C, v01 = B*conj(P), v10 = P*C, v11 = P*conj(P)
        const float v00r = Br * Cr - Bi * Ci, v00i = Br * Ci + Bi * Cr;
        const float v01r = Br * Pr + Bi * Pi, v01i = Bi * Pr - Br * Pi;
        const float v10r = Pr * Cr - Pi * Ci, v10i = Pr * Ci + Pi * Cr;
        const float v11r = Pr * Pr + Pi * Pi, v11i = 0.0f;

        wpack[n] = make_float2(wr, fmaf(wr, wr, wi * wi));
        vpack[n] = make_float4(dt * v00r, dt * v01r, dt * v10r, dt * v11r);
        upack[n] = make_float4(dt * fmaf(v00r, wr, v00i * wi),
                               dt * fmaf(v01r, wr, v01i * wi),
                               dt * fmaf(v10r, wr, v10i * wi),
                               dt * fmaf(v11r, wr, v11i * wi));
    }
    __syncthreads();

    // ---------------- Phase 2: Cauchy resolvent + Woodbury -> k_f[l] ----------
    // theta/2 = pi*l/L; c = cos, s = sin. Pair-folded, c-homogenized form:
    //   psi_n = (-2c*u + i*4s*vr) / (c^2|w|^2 - 4s^2 - i*4sc*wr)
    //   rho_ab = sum_n psi (dt folded into u, vr)
    //   k_f = [rho00 - c*rho01*rho10/(1 + c*rho11)] * (c + i*s)
    for (int l = tid; l < LF; l += NTHR) {
        float s, c;
        sincospif((float)l * (1.0f / (float)LL), &s, &c);
        const float c2   = c * c;
        const float ms4  = -4.0f * s * s;
        const float msc4 = -4.0f * s * c;

        float S0r = 0.f, S0i = 0.f, S1r = 0.f, S1i = 0.f;
        float S2r = 0.f, S2i = 0.f, S3r = 0.f, S3i = 0.f;
        float T0r = 0.f, T0i = 0.f, T1r = 0.f, T1i = 0.f;
        float T2r = 0.f, T2i = 0.f, T3r = 0.f, T3i = 0.f;

        #pragma unroll 8
        for (int n = 0; n < NN; n++) {
            const float2 wp = wpack[n];
            const float dr = fmaf(c2, wp.y, ms4);
            const float di = msc4 * wp.x;
            const float m  = fmaf(dr, dr, di * di);
            const float rm = frcp(m);
            const float ir = dr * rm;
            const float ii = -di * rm;
            const float4 u = upack[n];
            const float4 v = vpack[n];
            S0r = fmaf(u.x, ir, S0r); S0i = fmaf(u.x, ii, S0i);
            S1r = fmaf(u.y, ir, S1r); S1i = fmaf(u.y, ii, S1i);
            S2r = fmaf(u.z, ir, S2r); S2i = fmaf(u.z, ii, S2i);
            S3r = fmaf(u.w, ir, S3r); S3i = fmaf(u.w, ii, S3i);
            T0r = fmaf(v.x, ir, T0r); T0i = fmaf(v.x, ii, T0i);
            T1r = fmaf(v.y, ir, T1r); T1i = fmaf(v.y, ii, T1i);
            T2r = fmaf(v.z, ir, T2r); T2i = fmaf(v.z, ii, T2i);
            T3r = fmaf(v.w, ir, T3r); T3i = fmaf(v.w, ii, T3i);
        }

        const float tc = -2.0f * c, fs = 4.0f * s;
        const float r00r = fmaf(tc, S0r, -fs * T0i), r00i = fmaf(tc, S0i, fs * T0r);
        const float r01r = fmaf(tc, S1r, -fs * T1i), r01i = fmaf(tc, S1i, fs * T1r);
        const float r10r = fmaf(tc, S2r, -fs * T2i), r10i = fmaf(tc, S2i, fs * T2r);
        const float r11r = fmaf(tc, S3r, -fs * T3i), r11i = fmaf(tc, S3i, fs * T3r);

        // Woodbury: k = rho00 - c*rho01*rho10 / (1 + c*rho11)
        const float ddr = fmaf(c, r11r, 1.0f);
        const float ddi = c * r11i;
        const float dm  = frcp(fmaf(ddr, ddr, ddi * ddi));
        const float nr  = c * (r01r * r10r - r01i * r10i);
        const float ni  = c * (r01r * r10i + r01i * r10r);
        const float cr  = (nr * ddr + ni * ddi) * dm;
        const float ci  = (ni * ddr - nr * ddi) * dm;
        const float kr  = r00r - cr;
        const float ki  = r00i - ci;
        // multiply by (c + i s)  (== 2/(1+omega) with the 1/c absorbed)
        const float kfr = kr * c - ki * s;
        const float kfi = kr * s + ki * c;

        if (l < MM) fbuf[MM + l] = make_float2(kfr, kfi);
        else        kf_last      = make_float2(kfr, kfi);
    }
    __syncthreads();

    // ---------------- Phase 3: Hermitian pack -> half-size IFFT input Z -------
    // Z[k] = Xe[k] + i*Xo[k]
    //   Xe = (X[k] + conj(X[M-k]))/2
    //   Xo = e^{+2pi i k/L} * (X[k] - conj(X[M-k]))/2
    for (int k = tid; k < MM; k += NTHR) {
        const float2 Xk = fbuf[MM + k];
        const float2 Xm = (k == 0) ? kf_last : fbuf[MM + (MM - k)];
        const float er = 0.5f * (Xk.x + Xm.x);
        const float ei = 0.5f * (Xk.y - Xm.y);
        const float hr = 0.5f * (Xk.x - Xm.x);
        const float hi = 0.5f * (Xk.y + Xm.y);
        float tws, twc;
        sincospif((float)k * (1.0f / (float)MM), &tws, &twc);
        const float xor_ = twc * hr - tws * hi;
        const float xoi  = twc * hi + tws * hr;
        fbuf[k] = make_float2(er - xoi, ei + xor_);
    }
    __syncthreads();

    // ---------------- Phase 4: Stockham inverse FFT (size 2048, sign = +) ----
    int sb = 0;
    float invNs = 1.0f;
    for (int Ns = 1; Ns < MM; Ns <<= 1) {
        const int db = sb ^ MM;
        for (int j = tid; j < MM / 2; j += NTHR) {
            const float2 a = fbuf[sb + j];
            const float2 b = fbuf[sb + j + MM / 2];
            const int jm = j & (Ns - 1);
            float wy, wx;
            sincospif((float)jm * invNs, &wy, &wx);   // e^{+i*pi*jm/Ns}
            const float tr = fmaf(wx, b.x, -wy * b.y);
            const float ti = fmaf(wx, b.y,  wy * b.x);
            const int idxD = ((j - jm) << 1) + jm;
            fbuf[db + idxD]      = make_float2(a.x + tr, a.y + ti);
            fbuf[db + idxD + Ns] = make_float2(a.x - tr, a.y - ti);
        }
        __syncthreads();
        sb = db;
        invNs *= 0.5f;
    }

    // ---------------- Phase 5: unpack + scale + coalesced store ---------------
    // z[n] holds (x[2n], x[2n+1]) after 1/M scaling.
    float2* o = reinterpret_cast<float2*>(out) + (size_t)h * MM;
    const float scale = 1.0f / (float)MM;
    for (int n = tid; n < MM; n += NTHR) {
        const float2 z = fbuf[sb + n];
        o[n] = make_float2(z.x * scale, z.y * scale);
    }
}

extern "C" void kernel_launch(void* const* d_in, const int* in_sizes, int n_in,
                              void* d_out, int out_size)
{
    (void)in_sizes; (void)n_in; (void)out_size;
    const float* log_dt = (const float*)d_in[0];
    const float* A_re   = (const float*)d_in[1];
    const float* A_im   = (const float*)d_in[2];
    const float* B_re   = (const float*)d_in[3];
    const float* B_im   = (const float*)d_in[4];
    const float* C_re   = (const float*)d_in[5];
    const float* C_im   = (const float*)d_in[6];
    const float* P_re   = (const float*)d_in[7];
    const float* P_im   = (const float*)d_in[8];
    float* out = (float*)d_out;

    dplr_kernel<<<HH, NTHR>>>(log_dt, A_re, A_im, B_re, B_im,
                              C_re, C_im, P_re, P_im, out);
}